// round 14
// baseline (speedup 1.0000x reference)
#include <cuda_runtime.h>
#include <cuda_bf16.h>
#include <cuda_fp16.h>
#include <cstdint>

// ---------------------------------------------------------------------------
// SpatialGCN fused pipeline — mma.sync (HMMA) fp16 2-pass GEMMs.
// R10: BM=128 BN=256, 8 warps as 2(m) x 4(n), warp tile 64x64 ->
//      LDSM per MMA cut 1.65x (L1TEX was 75% and co-limiting).
// C = A @ B^T with A single fp16, B split fp16 hi/lo (2 passes).
// BN stats fused into GEMM0 epilogue.
// ---------------------------------------------------------------------------

#define NFRM   15552
#define R_ROWS (NFRM * 17)               // 264384
#define R_PAD  264448                    // 2066 * 128
#define MTILES (R_PAD / 128)             // 2066

// ---- scratch (static device globals, zero-initialized) ----
__device__ __half g_xa [(size_t)R_PAD * 256];   // aggregated input (fp16)
__device__ float  g_h  [(size_t)R_PAD * 256];   // post-GCN hidden fp32
__device__ __half g_hn [(size_t)R_PAD * 256];   // normalized hidden (fp16)
__device__ __half g_mid[(size_t)R_PAD * 512];   // MLP hidden (fp16)
__device__ __half g_Wh1[256 * 256], g_Wl1[256 * 256];   // (w1+w2) hi/lo
__device__ __half g_Wh2[512 * 256], g_Wl2[512 * 256];   // mlp_w1 hi/lo
__device__ __half g_Wh3[256 * 512], g_Wl3[256 * 512];   // mlp_w2 hi/lo
__device__ float g_biasJ[17 * 256];
__device__ float g_psum[MTILES * 256];
__device__ float g_pss [MTILES * 256];
__device__ float g_scale[256];
__device__ float g_shift[256];

// ---------------------------------------------------------------------------
// helpers
// ---------------------------------------------------------------------------
__device__ __forceinline__ uint32_t smem_u32(const void* p) {
    uint32_t a;
    asm("{ .reg .u64 t; cvta.to.shared.u64 t, %1; cvt.u32.u64 %0, t; }"
        : "=r"(a) : "l"(p));
    return a;
}
#define CP16(dst, src) \
    asm volatile("cp.async.cg.shared.global [%0], [%1], 16;" :: "r"(dst), "l"(src))
#define CP_COMMIT() asm volatile("cp.async.commit_group;" ::: "memory")
#define CP_WAIT0()  asm volatile("cp.async.wait_group 0;" ::: "memory")

__device__ __forceinline__ void ldsm4(uint32_t* r, uint32_t a) {
    asm volatile("ldmatrix.sync.aligned.m8n8.x4.shared.b16 {%0,%1,%2,%3}, [%4];"
        : "=r"(r[0]), "=r"(r[1]), "=r"(r[2]), "=r"(r[3]) : "r"(a));
}
__device__ __forceinline__ void mma16816(float* d, const uint32_t* a, const uint32_t* b) {
    asm volatile("mma.sync.aligned.m16n8k16.row.col.f32.f16.f16.f32 "
        "{%0,%1,%2,%3}, {%4,%5,%6,%7}, {%8,%9}, {%0,%1,%2,%3};"
        : "+f"(d[0]), "+f"(d[1]), "+f"(d[2]), "+f"(d[3])
        : "r"(a[0]), "r"(a[1]), "r"(a[2]), "r"(a[3]), "r"(b[0]), "r"(b[1]));
}
__device__ __forceinline__ uint32_t pack_h2(float a, float b) {
    __half2 t = __floats2half2_rn(a, b);
    return *reinterpret_cast<uint32_t*>(&t);
}

// ---------------------------------------------------------------------------
// prep: split weights into fp16 hi/lo; aggregated per-joint bias
// ---------------------------------------------------------------------------
__global__ void prep_w_kernel(const float* __restrict__ w1, const float* __restrict__ w2,
                              const float* __restrict__ mw1, const float* __restrict__ mw2)
{
    int i0 = blockIdx.x * blockDim.x + threadIdx.x;
    int st = gridDim.x * blockDim.x;
    for (int t = i0; t < 256 * 256; t += st) {
        float v = w1[t] + w2[t];
        __half h = __float2half_rn(v);
        g_Wh1[t] = h; g_Wl1[t] = __float2half_rn(v - __half2float(h));
    }
    for (int t = i0; t < 512 * 256; t += st) {
        float v = mw1[t];
        __half h = __float2half_rn(v);
        g_Wh2[t] = h; g_Wl2[t] = __float2half_rn(v - __half2float(h));
    }
    for (int t = i0; t < 256 * 512; t += st) {
        float v = mw2[t];
        __half h = __float2half_rn(v);
        g_Wh3[t] = h; g_Wl3[t] = __float2half_rn(v - __half2float(h));
    }
}

__global__ void prep_bias_kernel(const float* __restrict__ b1, const float* __restrict__ b2,
                                 const float* __restrict__ adj)
{
    int tid = threadIdx.x;
    __shared__ float c1[17], c2[17];
    if (tid < 17) {
        float s1 = 0.f, s2 = 0.f;
        #pragma unroll
        for (int j = 0; j < 17; j++) { s1 += adj[j * 17 + tid]; s2 += adj[tid * 17 + j]; }
        c1[tid] = s1; c2[tid] = s2;
    }
    __syncthreads();
    #pragma unroll
    for (int i = 0; i < 17; i++)
        g_biasJ[i * 256 + tid] = c1[i] * b1[tid] + c2[i] * b2[tid];
}

// ---------------------------------------------------------------------------
// agg: xa[n,i,:] = sum_j adj[i,j] x[n,j,:]  -> fp16
// ---------------------------------------------------------------------------
__global__ void agg_kernel(const float* __restrict__ x, const float* __restrict__ adj)
{
    __shared__ float xs[17][256];
    __shared__ float adjS[17][17];
    const int n = blockIdx.x;
    const int c = threadIdx.x;

    const float* xp = x + (size_t)n * 17 * 256;
    #pragma unroll
    for (int j = 0; j < 17; j++) xs[j][c] = xp[j * 256 + c];
    for (int idx = c; idx < 289; idx += 256)
        adjS[idx / 17][idx % 17] = adj[idx];
    __syncthreads();

    const size_t base = (size_t)n * 17 * 256 + c;
    #pragma unroll
    for (int i = 0; i < 17; i++) {
        float s = 0.f;
        #pragma unroll
        for (int j = 0; j < 17; j++) s += adjS[i][j] * xs[j][c];
        g_xa[base + i * 256] = __float2half_rn(s);
    }
}

// ---------------------------------------------------------------------------
// HMMA GEMM: C[128x256 tile] = A @ B^T, fp16 A + B hi/lo (2 passes).
// 8 warps as 2(m) x 4(n); warp tile 64x64. BK=64.
// Stage = A 16KB + Bh 32KB + Bl 32KB = 80KB; 2 stages; 1 CTA/SM.
//  MODE 0: A=xa  (K=256) B=Ws  -> g_h fp32 (+biasJ[row%17], ReLU) + BN stats
//  MODE 1: A=hn  (K=256) B=mw1 -> g_mid fp16 (+mb1, ReLU)
//  MODE 2: A=mid (K=512) B=mw2 -> out fp32 (+mb2), row-guarded
// ---------------------------------------------------------------------------
template <int MODE>
__global__ void __launch_bounds__(256, 1)
hmma_gemm_kernel(const float* __restrict__ biasp, float* __restrict__ Cp)
{
    constexpr int K   = (MODE == 2) ? 512 : 256;
    constexpr int NKC = K / 64;
    const __half* __restrict__ A  = (MODE == 0) ? g_xa  : (MODE == 1) ? g_hn  : g_mid;
    const __half* __restrict__ Bh = (MODE == 0) ? g_Wh1 : (MODE == 1) ? g_Wh2 : g_Wh3;
    const __half* __restrict__ Bl = (MODE == 0) ? g_Wl1 : (MODE == 1) ? g_Wl2 : g_Wl3;

    extern __shared__ char smem_raw[];
    char* sm = (char*)(((uintptr_t)smem_raw + 1023) & ~(uintptr_t)1023);
    const uint32_t sbase = smem_u32(sm);

    const int tid   = threadIdx.x;
    const int lane  = tid & 31;
    const int wid   = tid >> 5;
    const int warpM = wid & 1;          // 2 m-warps (64 rows each)
    const int warpN = wid >> 1;         // 4 n-warps (64 cols each)
    const int m0 = blockIdx.y * 128;
    const int n0 = blockIdx.x * 256;

    const int rA  = warpM * 64 + (lane & 15);
    const int cbA = lane >> 4;
    const int swA = rA & 7;
    const int rB  = warpN * 64 + ((lane >> 4) << 3) + (lane & 7);
    const int cbB = (lane >> 3) & 1;
    const int swB = lane & 7;

    // stage loader: A plane 16KB + Bh plane 32KB + Bl plane 32KB
    auto load_stage = [&](int stg, int kc) {
        const uint32_t sb = sbase + stg * 81920;
        const __half* pA  = A  + (size_t)m0 * K + kc * 64;
        const __half* pBh = Bh + (size_t)n0 * K + kc * 64;
        const __half* pBl = Bl + (size_t)n0 * K + kc * 64;
        #pragma unroll
        for (int i = tid; i < 1024; i += 256) {
            const int r = i >> 3, c = i & 7;
            const uint32_t d = (uint32_t)(r * 128 + ((c ^ (r & 7)) << 4));
            CP16(sb + d, (const char*)(pA + (size_t)r * K + c * 8));
        }
        #pragma unroll
        for (int i = tid; i < 2048; i += 256) {
            const int r = i >> 3, c = i & 7;
            const uint32_t d = (uint32_t)(r * 128 + ((c ^ (r & 7)) << 4));
            const size_t go = (size_t)r * K + c * 8;
            CP16(sb + 16384 + d, (const char*)(pBh + go));
            CP16(sb + 49152 + d, (const char*)(pBl + go));
        }
    };

    float acc[4][8][4];
    #pragma unroll
    for (int a = 0; a < 4; a++)
        #pragma unroll
        for (int b = 0; b < 8; b++)
            #pragma unroll
            for (int c = 0; c < 4; c++) acc[a][b][c] = 0.f;

    load_stage(0, 0); CP_COMMIT();

    for (int kc = 0; kc < NKC; kc++) {
        const int stg = kc & 1;
        CP_WAIT0();            // stage kc ready
        __syncthreads();       // + everyone done reading stage kc-1
        if (kc + 1 < NKC) load_stage(stg ^ 1, kc + 1);
        CP_COMMIT();

        const uint32_t sA  = sbase + stg * 81920;
        const uint32_t sBh = sA + 16384;
        const uint32_t sBl = sA + 49152;

        #pragma unroll
        for (int ks = 0; ks < 4; ks++) {
            uint32_t ah[4][4];
            const int hA = ks * 2 + cbA;
            const uint32_t cA = (uint32_t)((hA ^ swA) << 4);
            #pragma unroll
            for (int tm = 0; tm < 4; tm++)
                ldsm4(ah[tm], sA + (uint32_t)((rA + tm * 16) * 128) + cA);
            const int hB = ks * 2 + cbB;
            const uint32_t cB = (uint32_t)((hB ^ swB) << 4);
            #pragma unroll
            for (int pass = 0; pass < 2; pass++) {
                const uint32_t sB = pass ? sBl : sBh;
                #pragma unroll
                for (int tp = 0; tp < 4; tp++) {
                    uint32_t bb[4];
                    ldsm4(bb, sB + (uint32_t)((rB + tp * 16) * 128) + cB);
                    #pragma unroll
                    for (int tm = 0; tm < 4; tm++)
                        #pragma unroll
                        for (int j = 0; j < 2; j++)
                            mma16816(acc[tm][tp * 2 + j], ah[tm], &bb[j * 2]);
                }
            }
        }
    }

    // ---- epilogue: d0,d1 -> (row g, cols 2t,2t+1); d2,d3 -> row g+8 ----
    const int g = lane >> 2, t = lane & 3;
    float cs[16], cq[16];
    if (MODE == 0) {
        #pragma unroll
        for (int i = 0; i < 16; i++) { cs[i] = 0.f; cq[i] = 0.f; }
    }
    #pragma unroll
    for (int tm = 0; tm < 4; tm++) {
        const int row0 = m0 + warpM * 64 + tm * 16 + g;
        const int row1 = row0 + 8;
        #pragma unroll
        for (int nt = 0; nt < 8; nt++) {
            const int col = n0 + warpN * 64 + nt * 8 + t * 2;
            const float* d = acc[tm][nt];
            if (MODE == 0) {
                const float* bp0 = g_biasJ + (row0 % 17) * 256;
                const float* bp1 = g_biasJ + (row1 % 17) * 256;
                float2 v0, v1;
                v0.x = fmaxf(d[0] + bp0[col], 0.f);
                v0.y = fmaxf(d[1] + bp0[col + 1], 0.f);
                v1.x = fmaxf(d[2] + bp1[col], 0.f);
                v1.y = fmaxf(d[3] + bp1[col + 1], 0.f);
                *(float2*)&g_h[(size_t)row0 * 256 + col] = v0;
                *(float2*)&g_h[(size_t)row1 * 256 + col] = v1;
                const float m0v = (row0 < R_ROWS) ? 1.f : 0.f;
                const float m1v = (row1 < R_ROWS) ? 1.f : 0.f;
                cs[nt * 2 + 0] += m0v * v0.x + m1v * v1.x;
                cs[nt * 2 + 1] += m0v * v0.y + m1v * v1.y;
                cq[nt * 2 + 0] += m0v * v0.x * v0.x + m1v * v1.x * v1.x;
                cq[nt * 2 + 1] += m0v * v0.y * v0.y + m1v * v1.y * v1.y;
            } else if (MODE == 1) {
                const float b0 = biasp[col], b1 = biasp[col + 1];
                float v00 = fmaxf(d[0] + b0, 0.f), v01 = fmaxf(d[1] + b1, 0.f);
                float v10 = fmaxf(d[2] + b0, 0.f), v11 = fmaxf(d[3] + b1, 0.f);
                *(uint32_t*)&g_mid[(size_t)row0 * 512 + col] = pack_h2(v00, v01);
                *(uint32_t*)&g_mid[(size_t)row1 * 512 + col] = pack_h2(v10, v11);
            } else {
                const float b0 = biasp[col], b1 = biasp[col + 1];
                if (row0 < R_ROWS) {
                    float2 v; v.x = d[0] + b0; v.y = d[1] + b1;
                    *(float2*)&Cp[(size_t)row0 * 256 + col] = v;
                }
                if (row1 < R_ROWS) {
                    float2 v; v.x = d[2] + b0; v.y = d[3] + b1;
                    *(float2*)&Cp[(size_t)row1 * 256 + col] = v;
                }
            }
        }
    }

    if (MODE == 0) {
        // reduce over g (lanes sharing t): xor 4, 8, 16
        #pragma unroll
        for (int o = 4; o <= 16; o <<= 1) {
            #pragma unroll
            for (int i = 0; i < 16; i++) {
                cs[i] += __shfl_xor_sync(0xFFFFFFFFu, cs[i], o);
                cq[i] += __shfl_xor_sync(0xFFFFFFFFu, cq[i], o);
            }
        }
        __syncthreads();                       // all warps done with stage reads
        float* sred = (float*)sm;              // reuse stage smem: [2][256] s, [2][256] q
        if (g == 0) {
            #pragma unroll
            for (int nt = 0; nt < 8; nt++) {
                #pragma unroll
                for (int c = 0; c < 2; c++) {
                    const int ct = warpN * 64 + nt * 8 + t * 2 + c;
                    sred[warpM * 256 + ct]        = cs[nt * 2 + c];
                    sred[512 + warpM * 256 + ct]  = cq[nt * 2 + c];
                }
            }
        }
        __syncthreads();
        if (tid < 256) {
            float s = sred[tid] + sred[256 + tid];
            float q = sred[512 + tid] + sred[768 + tid];
            g_psum[(size_t)blockIdx.y * 256 + n0 + tid] = s;
            g_pss [(size_t)blockIdx.y * 256 + n0 + tid] = q;
        }
    }
}

// ---------------------------------------------------------------------------
// finalize: fold BN stats (per-channel over m-tile partials)
// ---------------------------------------------------------------------------
__global__ void finalize_kernel(const float* __restrict__ bn_gamma,
                                const float* __restrict__ bn_beta)
{
    const int c = threadIdx.x;
    float s = 0.f, ss = 0.f;
    for (int b = 0; b < MTILES; b++) { s += g_psum[b * 256 + c]; ss += g_pss[b * 256 + c]; }
    const float inv = 1.f / (float)R_ROWS;
    float mean = s * inv;
    float var  = ss * inv - mean * mean;
    float sc = bn_gamma[c] * rsqrtf(var + 1e-5f);
    g_scale[c] = sc;
    g_shift[c] = bn_beta[c] - mean * sc;
}

// ---------------------------------------------------------------------------
// norm: BN affine + LayerNorm, warp per row; writes fp16 for GEMM1.
// ---------------------------------------------------------------------------
__global__ void norm_kernel(const float* __restrict__ ln_g,
                            const float* __restrict__ ln_b)
{
    const int row  = blockIdx.x * 8 + (threadIdx.x >> 5);
    const int lane = threadIdx.x & 31;
    if (row >= R_ROWS) return;
    const float* rp = g_h + (size_t)row * 256;
    const int c0 = lane * 8;

    float4 v0 = *(const float4*)&rp[c0];
    float4 v1 = *(const float4*)&rp[c0 + 4];
    float4 s0 = *(const float4*)&g_scale[c0];
    float4 s1 = *(const float4*)&g_scale[c0 + 4];
    float4 h0 = *(const float4*)&g_shift[c0];
    float4 h1 = *(const float4*)&g_shift[c0 + 4];

    float w[8];
    w[0] = v0.x * s0.x + h0.x; w[1] = v0.y * s0.y + h0.y;
    w[2] = v0.z * s0.z + h0.z; w[3] = v0.w * s0.w + h0.w;
    w[4] = v1.x * s1.x + h1.x; w[5] = v1.y * s1.y + h1.y;
    w[6] = v1.z * s1.z + h1.z; w[7] = v1.w * s1.w + h1.w;

    float sum = 0.f, ssq = 0.f;
    #pragma unroll
    for (int i = 0; i < 8; i++) { sum += w[i]; ssq += w[i] * w[i]; }
    #pragma unroll
    for (int o = 16; o > 0; o >>= 1) {
        sum += __shfl_xor_sync(0xFFFFFFFFu, sum, o);
        ssq += __shfl_xor_sync(0xFFFFFFFFu, ssq, o);
    }
    const float mean = sum * (1.f / 256.f);
    const float var  = ssq * (1.f / 256.f) - mean * mean;
    const float rs   = rsqrtf(var + 1e-5f);

    float4 g0 = *(const float4*)&ln_g[c0];
    float4 g1 = *(const float4*)&ln_g[c0 + 4];
    float4 t0 = *(const float4*)&ln_b[c0];
    float4 t1 = *(const float4*)&ln_b[c0 + 4];
    float gg[8] = {g0.x, g0.y, g0.z, g0.w, g1.x, g1.y, g1.z, g1.w};
    float bb[8] = {t0.x, t0.y, t0.z, t0.w, t1.x, t1.y, t1.z, t1.w};

    float of[8];
    #pragma unroll
    for (int i = 0; i < 8; i++)
        of[i] = (w[i] - mean) * rs * gg[i] + bb[i];
    uint4 ph;
    ph.x = pack_h2(of[0], of[1]); ph.y = pack_h2(of[2], of[3]);
    ph.z = pack_h2(of[4], of[5]); ph.w = pack_h2(of[6], of[7]);
    *(uint4*)&g_hn[(size_t)row * 256 + c0] = ph;
}

// ---------------------------------------------------------------------------
// launch
// ---------------------------------------------------------------------------
#define SMEM_DYN (1024 + 2 * 81920)   // align slack + 2 stages x 80KB = 164864

extern "C" void kernel_launch(void* const* d_in, const int* in_sizes, int n_in,
                              void* d_out, int out_size)
{
    const float* x    = (const float*)d_in[0];
    const float* adj  = (const float*)d_in[1];
    const float* w1   = (const float*)d_in[2];
    const float* b1   = (const float*)d_in[3];
    const float* w2   = (const float*)d_in[4];
    const float* b2   = (const float*)d_in[5];
    const float* bn_g = (const float*)d_in[6];
    const float* bn_b = (const float*)d_in[7];
    const float* ln_g = (const float*)d_in[8];
    const float* ln_b = (const float*)d_in[9];
    const float* mw1  = (const float*)d_in[10];
    const float* mb1  = (const float*)d_in[11];
    const float* mw2  = (const float*)d_in[12];
    const float* mb2  = (const float*)d_in[13];
    float* out = (float*)d_out;

    cudaFuncSetAttribute(hmma_gemm_kernel<0>, cudaFuncAttributeMaxDynamicSharedMemorySize, SMEM_DYN);
    cudaFuncSetAttribute(hmma_gemm_kernel<1>, cudaFuncAttributeMaxDynamicSharedMemorySize, SMEM_DYN);
    cudaFuncSetAttribute(hmma_gemm_kernel<2>, cudaFuncAttributeMaxDynamicSharedMemorySize, SMEM_DYN);

    prep_w_kernel<<<128, 256>>>(w1, w2, mw1, mw2);
    prep_bias_kernel<<<1, 256>>>(b1, b2, adj);
    agg_kernel<<<NFRM, 256>>>(x, adj);

    hmma_gemm_kernel<0><<<dim3(1, MTILES), 256, SMEM_DYN>>>(nullptr, nullptr);

    finalize_kernel<<<1, 256>>>(bn_g, bn_b);
    norm_kernel<<<(R_ROWS + 7) / 8, 256>>>(ln_g, ln_b);

    hmma_gemm_kernel<1><<<dim3(2, MTILES), 256, SMEM_DYN>>>(mb1, nullptr);
    hmma_gemm_kernel<2><<<dim3(1, MTILES), 256, SMEM_DYN>>>(mb2, out);
}

// round 16
// speedup vs baseline: 1.4330x; 1.4330x over previous
#include <cuda_runtime.h>
#include <cuda_bf16.h>
#include <cuda_fp16.h>
#include <cstdint>

// ---------------------------------------------------------------------------
// SpatialGCN fused pipeline — mma.sync (HMMA) single-pass fp16 GEMMs.
// R16 = R15 with the launch-grid fix: GEMM0 is BN=128 over N=256 -> grid.x=2
// (R15 launched grid.x=1, leaving cols 128..255 unwritten -> rel_err 0.697).
// Config: BM=128 BN=128 BK=64, 4(m)x2(n) warps, 2 stages x 32KB, 2 CTAs/SM.
// Fragment double-buffering: B one tp ahead, A one ks ahead.
// BN stats fused into GEMM0 epilogue.
// ---------------------------------------------------------------------------

#define NFRM   15552
#define R_ROWS (NFRM * 17)               // 264384
#define R_PAD  264448                    // 2066 * 128
#define MTILES (R_PAD / 128)             // 2066

// ---- scratch (static device globals, zero-initialized) ----
__device__ __half g_xa [(size_t)R_PAD * 256];   // aggregated input (fp16)
__device__ float  g_h  [(size_t)R_PAD * 256];   // post-GCN hidden fp32
__device__ __half g_hn [(size_t)R_PAD * 256];   // normalized hidden (fp16)
__device__ __half g_mid[(size_t)R_PAD * 512];   // MLP hidden (fp16)
__device__ __half g_W1[256 * 256];              // (w1+w2) fp16
__device__ __half g_W2[512 * 256];              // mlp_w1 fp16
__device__ __half g_W3[256 * 512];              // mlp_w2 fp16
__device__ float g_biasJ[17 * 256];
__device__ float g_psum[MTILES * 256];
__device__ float g_pss [MTILES * 256];
__device__ float g_scale[256];
__device__ float g_shift[256];

// ---------------------------------------------------------------------------
// helpers
// ---------------------------------------------------------------------------
__device__ __forceinline__ uint32_t smem_u32(const void* p) {
    uint32_t a;
    asm("{ .reg .u64 t; cvta.to.shared.u64 t, %1; cvt.u32.u64 %0, t; }"
        : "=r"(a) : "l"(p));
    return a;
}
#define CP16(dst, src) \
    asm volatile("cp.async.cg.shared.global [%0], [%1], 16;" :: "r"(dst), "l"(src))
#define CP_COMMIT() asm volatile("cp.async.commit_group;" ::: "memory")
#define CP_WAIT0()  asm volatile("cp.async.wait_group 0;" ::: "memory")

__device__ __forceinline__ void ldsm4(uint32_t* r, uint32_t a) {
    asm volatile("ldmatrix.sync.aligned.m8n8.x4.shared.b16 {%0,%1,%2,%3}, [%4];"
        : "=r"(r[0]), "=r"(r[1]), "=r"(r[2]), "=r"(r[3]) : "r"(a));
}
__device__ __forceinline__ void mma16816(float* d, const uint32_t* a, const uint32_t* b) {
    asm volatile("mma.sync.aligned.m16n8k16.row.col.f32.f16.f16.f32 "
        "{%0,%1,%2,%3}, {%4,%5,%6,%7}, {%8,%9}, {%0,%1,%2,%3};"
        : "+f"(d[0]), "+f"(d[1]), "+f"(d[2]), "+f"(d[3])
        : "r"(a[0]), "r"(a[1]), "r"(a[2]), "r"(a[3]), "r"(b[0]), "r"(b[1]));
}
__device__ __forceinline__ uint32_t pack_h2(float a, float b) {
    __half2 t = __floats2half2_rn(a, b);
    return *reinterpret_cast<uint32_t*>(&t);
}

// ---------------------------------------------------------------------------
// prep: weights -> fp16; aggregated per-joint bias
// ---------------------------------------------------------------------------
__global__ void prep_w_kernel(const float* __restrict__ w1, const float* __restrict__ w2,
                              const float* __restrict__ mw1, const float* __restrict__ mw2)
{
    int i0 = blockIdx.x * blockDim.x + threadIdx.x;
    int st = gridDim.x * blockDim.x;
    for (int t = i0; t < 256 * 256; t += st)
        g_W1[t] = __float2half_rn(w1[t] + w2[t]);
    for (int t = i0; t < 512 * 256; t += st)
        g_W2[t] = __float2half_rn(mw1[t]);
    for (int t = i0; t < 256 * 512; t += st)
        g_W3[t] = __float2half_rn(mw2[t]);
}

__global__ void prep_bias_kernel(const float* __restrict__ b1, const float* __restrict__ b2,
                                 const float* __restrict__ adj)
{
    int tid = threadIdx.x;
    __shared__ float c1[17], c2[17];
    if (tid < 17) {
        float s1 = 0.f, s2 = 0.f;
        #pragma unroll
        for (int j = 0; j < 17; j++) { s1 += adj[j * 17 + tid]; s2 += adj[tid * 17 + j]; }
        c1[tid] = s1; c2[tid] = s2;
    }
    __syncthreads();
    #pragma unroll
    for (int i = 0; i < 17; i++)
        g_biasJ[i * 256 + tid] = c1[i] * b1[tid] + c2[i] * b2[tid];
}

// ---------------------------------------------------------------------------
// agg: xa[n,i,:] = sum_j adj[i,j] x[n,j,:]  -> fp16
// ---------------------------------------------------------------------------
__global__ void agg_kernel(const float* __restrict__ x, const float* __restrict__ adj)
{
    __shared__ float xs[17][256];
    __shared__ float adjS[17][17];
    const int n = blockIdx.x;
    const int c = threadIdx.x;

    const float* xp = x + (size_t)n * 17 * 256;
    #pragma unroll
    for (int j = 0; j < 17; j++) xs[j][c] = xp[j * 256 + c];
    for (int idx = c; idx < 289; idx += 256)
        adjS[idx / 17][idx % 17] = adj[idx];
    __syncthreads();

    const size_t base = (size_t)n * 17 * 256 + c;
    #pragma unroll
    for (int i = 0; i < 17; i++) {
        float s = 0.f;
        #pragma unroll
        for (int j = 0; j < 17; j++) s += adjS[i][j] * xs[j][c];
        g_xa[base + i * 256] = __float2half_rn(s);
    }
}

// ---------------------------------------------------------------------------
// HMMA GEMM: C[128x128 tile] = A @ B^T, single fp16 pass.
// 8 warps as 4(m) x 2(n); warp tile 32x64. BK=64.
// Stage = A 16KB + B 16KB = 32KB; 2 stages; 2 CTAs/SM.
// Fragment pipeline: bb double-buffered (one tp ahead), ah one ks ahead.
//  MODE 0: A=xa  (K=256) B=W1 -> g_h fp32 (+biasJ[row%17], ReLU) + BN stats
//  MODE 1: A=hn  (K=256) B=W2 -> g_mid fp16 (+mb1, ReLU)
//  MODE 2: A=mid (K=512) B=W3 -> out fp32 (+mb2), row-guarded
// ---------------------------------------------------------------------------
template <int MODE>
__global__ void __launch_bounds__(256, 2)
hmma_gemm_kernel(const float* __restrict__ biasp, float* __restrict__ Cp)
{
    constexpr int K   = (MODE == 2) ? 512 : 256;
    constexpr int NKC = K / 64;
    const __half* __restrict__ A = (MODE == 0) ? g_xa : (MODE == 1) ? g_hn : g_mid;
    const __half* __restrict__ B = (MODE == 0) ? g_W1 : (MODE == 1) ? g_W2 : g_W3;

    extern __shared__ char smem_raw[];
    char* sm = (char*)(((uintptr_t)smem_raw + 1023) & ~(uintptr_t)1023);
    const uint32_t sbase = smem_u32(sm);

    const int tid   = threadIdx.x;
    const int lane  = tid & 31;
    const int wid   = tid >> 5;
    const int warpM = wid & 3;          // 4 m-warps (32 rows each)
    const int warpN = wid >> 2;         // 2 n-warps (64 cols each)
    const int m0 = blockIdx.y * 128;
    const int n0 = blockIdx.x * 128;

    const int rA  = warpM * 32 + (lane & 15);
    const int cbA = lane >> 4;
    const int swA = rA & 7;
    const int rB  = warpN * 64 + ((lane >> 4) << 3) + (lane & 7);
    const int cbB = (lane >> 3) & 1;
    const int swB = lane & 7;

    // stage loader: A plane 16KB + B plane 16KB
    auto load_stage = [&](int stg, int kc) {
        const uint32_t sb = sbase + stg * 32768;
        const __half* pA = A + (size_t)m0 * K + kc * 64;
        const __half* pB = B + (size_t)n0 * K + kc * 64;
        #pragma unroll
        for (int i = tid; i < 1024; i += 256) {
            const int r = i >> 3, c = i & 7;
            const uint32_t d = (uint32_t)(r * 128 + ((c ^ (r & 7)) << 4));
            const size_t go = (size_t)r * K + c * 8;
            CP16(sb + d,         (const char*)(pA + go));
            CP16(sb + 16384 + d, (const char*)(pB + go));
        }
    };

    float acc[2][8][4];
    #pragma unroll
    for (int a = 0; a < 2; a++)
        #pragma unroll
        for (int b = 0; b < 8; b++)
            #pragma unroll
            for (int c = 0; c < 4; c++) acc[a][b][c] = 0.f;

    load_stage(0, 0); CP_COMMIT();

    for (int kc = 0; kc < NKC; kc++) {
        const int stg = kc & 1;
        CP_WAIT0();            // stage kc ready
        __syncthreads();       // + everyone done reading stage kc-1
        if (kc + 1 < NKC) load_stage(stg ^ 1, kc + 1);
        CP_COMMIT();

        const uint32_t sA = sbase + stg * 32768;
        const uint32_t sB = sA + 16384;

        uint32_t ah[2][4], ahn[2][4], bb[2][4];
        // preload ks=0 fragments
        {
            const uint32_t cA0 = (uint32_t)((cbA ^ swA) << 4);
            ldsm4(ah[0], sA + (uint32_t)(rA * 128) + cA0);
            ldsm4(ah[1], sA + (uint32_t)((rA + 16) * 128) + cA0);
            const uint32_t cB0 = (uint32_t)((cbB ^ swB) << 4);
            ldsm4(bb[0], sB + (uint32_t)(rB * 128) + cB0);
        }
        #pragma unroll
        for (int ks = 0; ks < 4; ks++) {
            #pragma unroll
            for (int tp = 0; tp < 4; tp++) {
                // prefetch next B fragment (tp+1, or next ks's tp0)
                if (tp < 3) {
                    const uint32_t cB = (uint32_t)(((ks * 2 + cbB) ^ swB) << 4);
                    ldsm4(bb[(tp + 1) & 1], sB + (uint32_t)((rB + (tp + 1) * 16) * 128) + cB);
                } else if (ks < 3) {
                    const uint32_t cB = (uint32_t)((((ks + 1) * 2 + cbB) ^ swB) << 4);
                    ldsm4(bb[0], sB + (uint32_t)(rB * 128) + cB);
                }
                // prefetch next ks's A fragments early in the tp stream
                if (tp == 0 && ks < 3) {
                    const uint32_t cAn = (uint32_t)((((ks + 1) * 2 + cbA) ^ swA) << 4);
                    ldsm4(ahn[0], sA + (uint32_t)(rA * 128) + cAn);
                    ldsm4(ahn[1], sA + (uint32_t)((rA + 16) * 128) + cAn);
                }
                #pragma unroll
                for (int tm = 0; tm < 2; tm++)
                    #pragma unroll
                    for (int j = 0; j < 2; j++)
                        mma16816(acc[tm][tp * 2 + j], ah[tm], &bb[tp & 1][j * 2]);
            }
            if (ks < 3) {
                #pragma unroll
                for (int tm = 0; tm < 2; tm++)
                    #pragma unroll
                    for (int q = 0; q < 4; q++) ah[tm][q] = ahn[tm][q];
            }
        }
    }

    // ---- epilogue: d0,d1 -> (row g, cols 2t,2t+1); d2,d3 -> row g+8 ----
    const int g = lane >> 2, t = lane & 3;
    float cs[16], cq[16];
    if (MODE == 0) {
        #pragma unroll
        for (int i = 0; i < 16; i++) { cs[i] = 0.f; cq[i] = 0.f; }
    }
    #pragma unroll
    for (int tm = 0; tm < 2; tm++) {
        const int row0 = m0 + warpM * 32 + tm * 16 + g;
        const int row1 = row0 + 8;
        #pragma unroll
        for (int nt = 0; nt < 8; nt++) {
            const int col = n0 + warpN * 64 + nt * 8 + t * 2;
            const float* d = acc[tm][nt];
            if (MODE == 0) {
                const float* bp0 = g_biasJ + (row0 % 17) * 256;
                const float* bp1 = g_biasJ + (row1 % 17) * 256;
                float2 v0, v1;
                v0.x = fmaxf(d[0] + bp0[col], 0.f);
                v0.y = fmaxf(d[1] + bp0[col + 1], 0.f);
                v1.x = fmaxf(d[2] + bp1[col], 0.f);
                v1.y = fmaxf(d[3] + bp1[col + 1], 0.f);
                *(float2*)&g_h[(size_t)row0 * 256 + col] = v0;
                *(float2*)&g_h[(size_t)row1 * 256 + col] = v1;
                const float m0v = (row0 < R_ROWS) ? 1.f : 0.f;
                const float m1v = (row1 < R_ROWS) ? 1.f : 0.f;
                cs[nt * 2 + 0] += m0v * v0.x + m1v * v1.x;
                cs[nt * 2 + 1] += m0v * v0.y + m1v * v1.y;
                cq[nt * 2 + 0] += m0v * v0.x * v0.x + m1v * v1.x * v1.x;
                cq[nt * 2 + 1] += m0v * v0.y * v0.y + m1v * v1.y * v1.y;
            } else if (MODE == 1) {
                const float b0 = biasp[col], b1 = biasp[col + 1];
                float v00 = fmaxf(d[0] + b0, 0.f), v01 = fmaxf(d[1] + b1, 0.f);
                float v10 = fmaxf(d[2] + b0, 0.f), v11 = fmaxf(d[3] + b1, 0.f);
                *(uint32_t*)&g_mid[(size_t)row0 * 512 + col] = pack_h2(v00, v01);
                *(uint32_t*)&g_mid[(size_t)row1 * 512 + col] = pack_h2(v10, v11);
            } else {
                const float b0 = biasp[col], b1 = biasp[col + 1];
                if (row0 < R_ROWS) {
                    float2 v; v.x = d[0] + b0; v.y = d[1] + b1;
                    *(float2*)&Cp[(size_t)row0 * 256 + col] = v;
                }
                if (row1 < R_ROWS) {
                    float2 v; v.x = d[2] + b0; v.y = d[3] + b1;
                    *(float2*)&Cp[(size_t)row1 * 256 + col] = v;
                }
            }
        }
    }

    if (MODE == 0) {
        // reduce over g (lanes sharing t): xor 4, 8, 16
        #pragma unroll
        for (int o = 4; o <= 16; o <<= 1) {
            #pragma unroll
            for (int i = 0; i < 16; i++) {
                cs[i] += __shfl_xor_sync(0xFFFFFFFFu, cs[i], o);
                cq[i] += __shfl_xor_sync(0xFFFFFFFFu, cq[i], o);
            }
        }
        __syncthreads();                       // all warps done with stage reads
        float* sred = (float*)sm;              // reuse stage smem: [4][128] s, [4][128] q
        if (g == 0) {
            #pragma unroll
            for (int nt = 0; nt < 8; nt++) {
                #pragma unroll
                for (int c = 0; c < 2; c++) {
                    const int ct = warpN * 64 + nt * 8 + t * 2 + c;
                    sred[warpM * 128 + ct]       = cs[nt * 2 + c];
                    sred[512 + warpM * 128 + ct] = cq[nt * 2 + c];
                }
            }
        }
        __syncthreads();
        if (tid < 128) {
            float s = sred[tid] + sred[128 + tid] + sred[256 + tid] + sred[384 + tid];
            float q = sred[512 + tid] + sred[640 + tid] + sred[768 + tid] + sred[896 + tid];
            const int gcol = n0 + tid;
            g_psum[(size_t)blockIdx.y * 256 + gcol] = s;
            g_pss [(size_t)blockIdx.y * 256 + gcol] = q;
        }
    }
}

// ---------------------------------------------------------------------------
// finalize: fold BN stats (per-channel over m-tile partials)
// ---------------------------------------------------------------------------
__global__ void finalize_kernel(const float* __restrict__ bn_gamma,
                                const float* __restrict__ bn_beta)
{
    const int c = threadIdx.x;
    float s = 0.f, ss = 0.f;
    for (int b = 0; b < MTILES; b++) { s += g_psum[b * 256 + c]; ss += g_pss[b * 256 + c]; }
    const float inv = 1.f / (float)R_ROWS;
    float mean = s * inv;
    float var  = ss * inv - mean * mean;
    float sc = bn_gamma[c] * rsqrtf(var + 1e-5f);
    g_scale[c] = sc;
    g_shift[c] = bn_beta[c] - mean * sc;
}

// ---------------------------------------------------------------------------
// norm: BN affine + LayerNorm, warp per row; writes fp16 for GEMM1.
// ---------------------------------------------------------------------------
__global__ void norm_kernel(const float* __restrict__ ln_g,
                            const float* __restrict__ ln_b)
{
    const int row  = blockIdx.x * 8 + (threadIdx.x >> 5);
    const int lane = threadIdx.x & 31;
    if (row >= R_ROWS) return;
    const float* rp = g_h + (size_t)row * 256;
    const int c0 = lane * 8;

    float4 v0 = *(const float4*)&rp[c0];
    float4 v1 = *(const float4*)&rp[c0 + 4];
    float4 s0 = *(const float4*)&g_scale[c0];
    float4 s1 = *(const float4*)&g_scale[c0 + 4];
    float4 h0 = *(const float4*)&g_shift[c0];
    float4 h1 = *(const float4*)&g_shift[c0 + 4];

    float w[8];
    w[0] = v0.x * s0.x + h0.x; w[1] = v0.y * s0.y + h0.y;
    w[2] = v0.z * s0.z + h0.z; w[3] = v0.w * s0.w + h0.w;
    w[4] = v1.x * s1.x + h1.x; w[5] = v1.y * s1.y + h1.y;
    w[6] = v1.z * s1.z + h1.z; w[7] = v1.w * s1.w + h1.w;

    float sum = 0.f, ssq = 0.f;
    #pragma unroll
    for (int i = 0; i < 8; i++) { sum += w[i]; ssq += w[i] * w[i]; }
    #pragma unroll
    for (int o = 16; o > 0; o >>= 1) {
        sum += __shfl_xor_sync(0xFFFFFFFFu, sum, o);
        ssq += __shfl_xor_sync(0xFFFFFFFFu, ssq, o);
    }
    const float mean = sum * (1.f / 256.f);
    const float var  = ssq * (1.f / 256.f) - mean * mean;
    const float rs   = rsqrtf(var + 1e-5f);

    float4 g0 = *(const float4*)&ln_g[c0];
    float4 g1 = *(const float4*)&ln_g[c0 + 4];
    float4 t0 = *(const float4*)&ln_b[c0];
    float4 t1 = *(const float4*)&ln_b[c0 + 4];
    float gg[8] = {g0.x, g0.y, g0.z, g0.w, g1.x, g1.y, g1.z, g1.w};
    float bb[8] = {t0.x, t0.y, t0.z, t0.w, t1.x, t1.y, t1.z, t1.w};

    float of[8];
    #pragma unroll
    for (int i = 0; i < 8; i++)
        of[i] = (w[i] - mean) * rs * gg[i] + bb[i];
    uint4 ph;
    ph.x = pack_h2(of[0], of[1]); ph.y = pack_h2(of[2], of[3]);
    ph.z = pack_h2(of[4], of[5]); ph.w = pack_h2(of[6], of[7]);
    *(uint4*)&g_hn[(size_t)row * 256 + c0] = ph;
}

// ---------------------------------------------------------------------------
// launch
// ---------------------------------------------------------------------------
#define SMEM_DYN (1024 + 2 * 32768)   // align slack + 2 stages x 32KB = 66560

extern "C" void kernel_launch(void* const* d_in, const int* in_sizes, int n_in,
                              void* d_out, int out_size)
{
    const float* x    = (const float*)d_in[0];
    const float* adj  = (const float*)d_in[1];
    const float* w1   = (const float*)d_in[2];
    const float* b1   = (const float*)d_in[3];
    const float* w2   = (const float*)d_in[4];
    const float* b2   = (const float*)d_in[5];
    const float* bn_g = (const float*)d_in[6];
    const float* bn_b = (const float*)d_in[7];
    const float* ln_g = (const float*)d_in[8];
    const float* ln_b = (const float*)d_in[9];
    const float* mw1  = (const float*)d_in[10];
    const float* mb1  = (const float*)d_in[11];
    const float* mw2  = (const float*)d_in[12];
    const float* mb2  = (const float*)d_in[13];
    float* out = (float*)d_out;

    cudaFuncSetAttribute(hmma_gemm_kernel<0>, cudaFuncAttributeMaxDynamicSharedMemorySize, SMEM_DYN);
    cudaFuncSetAttribute(hmma_gemm_kernel<1>, cudaFuncAttributeMaxDynamicSharedMemorySize, SMEM_DYN);
    cudaFuncSetAttribute(hmma_gemm_kernel<2>, cudaFuncAttributeMaxDynamicSharedMemorySize, SMEM_DYN);

    prep_w_kernel<<<128, 256>>>(w1, w2, mw1, mw2);
    prep_bias_kernel<<<1, 256>>>(b1, b2, adj);
    agg_kernel<<<NFRM, 256>>>(x, adj);

    // FIX (R16): N=256 with BN=128 -> grid.x = 2 (was 1 in R15 -> half of g_h
    // never written, BN var=0 on cols 128..255, rel_err 0.697).
    hmma_gemm_kernel<0><<<dim3(2, MTILES), 256, SMEM_DYN>>>(nullptr, nullptr);

    finalize_kernel<<<1, 256>>>(bn_g, bn_b);
    norm_kernel<<<(R_ROWS + 7) / 8, 256>>>(ln_g, ln_b);

    hmma_gemm_kernel<1><<<dim3(4, MTILES), 256, SMEM_DYN>>>(mb1, nullptr);
    hmma_gemm_kernel<2><<<dim3(2, MTILES), 256, SMEM_DYN>>>(mb2, out);
}